// round 13
// baseline (speedup 1.0000x reference)
#include <cuda_runtime.h>
#include <cstdint>

// MeanAggregator: out[i] = sum_{j in edges[i]} nodes[edges[i][j]] / n_nodes
// Shapes: N = 40000, DEG = 16, D = 128 (fp32); edges buffer is int32.
//
// R13 (= R12 resubmit after infra failure): the regs=32 invariant of R4-R11
// was self-inflicted: __launch_bounds__(256) with no minBlocks makes ptxas
// budget 65536/2048 = 32 regs/thread, which cannot hold 16 gather addresses
// -> MLP_eff pinned at ~4 regardless of source structure.
// __launch_bounds__(256, 2) lifts the ceiling to 128 regs so ptxas can
// front-batch the 16 independent float4 gathers (true MLP window).

#define D_FEAT 128
#define D_VEC (D_FEAT / 4)   // 32 float4 per row = 1 per lane
#define DEG_FAST 16

__global__ __launch_bounds__(256, 2) void gather_mean_r13_kernel(
    const float4* __restrict__ nodes,   // [n_nodes * 32] float4
    const int* __restrict__ edges,      // [n_nodes * deg] int32
    float4* __restrict__ out,           // [n_nodes * 32] float4
    int n_nodes, int deg, float inv_n)
{
    const int warp_id = (blockIdx.x * blockDim.x + threadIdx.x) >> 5;
    const int lane = threadIdx.x & 31;
    if (warp_id >= n_nodes) return;

    float4 acc = make_float4(0.f, 0.f, 0.f, 0.f);

    if (deg == DEG_FAST) {
        // Index fetch: 4 x int4 (uniform across warp -> broadcast LDG).
        const int4* e4 = (const int4*)(edges + (long long)warp_id * DEG_FAST);
        int idx[DEG_FAST];
#pragma unroll
        for (int q = 0; q < 4; ++q) {
            int4 a = __ldg(&e4[q]);
            idx[q * 4 + 0] = a.x; idx[q * 4 + 1] = a.y;
            idx[q * 4 + 2] = a.z; idx[q * 4 + 3] = a.w;
        }

        // 16 independent float4 gathers into distinct destinations, then a
        // pairwise tree. With a 128-reg budget ptxas can front-batch these.
        float4 v[DEG_FAST];
#pragma unroll
        for (int j = 0; j < DEG_FAST; ++j) {
            v[j] = __ldg(&nodes[(size_t)(unsigned)idx[j] * D_VEC + lane]);
        }

        float4 s[8];
#pragma unroll
        for (int j = 0; j < 8; ++j) {
            s[j].x = v[2 * j].x + v[2 * j + 1].x;
            s[j].y = v[2 * j].y + v[2 * j + 1].y;
            s[j].z = v[2 * j].z + v[2 * j + 1].z;
            s[j].w = v[2 * j].w + v[2 * j + 1].w;
        }
        float4 t[4];
#pragma unroll
        for (int j = 0; j < 4; ++j) {
            t[j].x = s[2 * j].x + s[2 * j + 1].x;
            t[j].y = s[2 * j].y + s[2 * j + 1].y;
            t[j].z = s[2 * j].z + s[2 * j + 1].z;
            t[j].w = s[2 * j].w + s[2 * j + 1].w;
        }
        acc.x = (t[0].x + t[1].x) + (t[2].x + t[3].x);
        acc.y = (t[0].y + t[1].y) + (t[2].y + t[3].y);
        acc.z = (t[0].z + t[1].z) + (t[2].z + t[3].z);
        acc.w = (t[0].w + t[1].w) + (t[2].w + t[3].w);
    } else {
        // Generic fallback: unroll by 4.
        const int* e = edges + (long long)warp_id * deg;
        int j = 0;
        for (; j + 4 <= deg; j += 4) {
            int i0 = __ldg(&e[j + 0]);
            int i1 = __ldg(&e[j + 1]);
            int i2 = __ldg(&e[j + 2]);
            int i3 = __ldg(&e[j + 3]);
            float4 v0 = __ldg(&nodes[(size_t)(unsigned)i0 * D_VEC + lane]);
            float4 v1 = __ldg(&nodes[(size_t)(unsigned)i1 * D_VEC + lane]);
            float4 v2 = __ldg(&nodes[(size_t)(unsigned)i2 * D_VEC + lane]);
            float4 v3 = __ldg(&nodes[(size_t)(unsigned)i3 * D_VEC + lane]);
            acc.x += (v0.x + v1.x) + (v2.x + v3.x);
            acc.y += (v0.y + v1.y) + (v2.y + v3.y);
            acc.z += (v0.z + v1.z) + (v2.z + v3.z);
            acc.w += (v0.w + v1.w) + (v2.w + v3.w);
        }
        for (; j < deg; ++j) {
            int i0 = __ldg(&e[j]);
            float4 v = __ldg(&nodes[(size_t)(unsigned)i0 * D_VEC + lane]);
            acc.x += v.x; acc.y += v.y; acc.z += v.z; acc.w += v.w;
        }
    }

    out[(long long)warp_id * D_VEC + lane] =
        make_float4(acc.x * inv_n, acc.y * inv_n, acc.z * inv_n, acc.w * inv_n);
}

extern "C" void kernel_launch(void* const* d_in, const int* in_sizes, int n_in,
                              void* d_out, int out_size)
{
    const float4* nodes = (const float4*)d_in[0];
    const int* edges = (const int*)d_in[1];
    float4* out = (float4*)d_out;

    const int n_nodes = in_sizes[0] / D_FEAT;
    const int deg = in_sizes[1] / n_nodes;
    const float inv_n = 1.0f / (float)n_nodes;

    // One warp per node, 8 warps (256 threads) per block.
    const int threads = 256;
    const int warps_per_block = threads / 32;
    const int blocks = (n_nodes + warps_per_block - 1) / warps_per_block;  // 5000
    gather_mean_r13_kernel<<<blocks, threads>>>(nodes, edges, out,
                                                n_nodes, deg, inv_n);
}

// round 14
// speedup vs baseline: 1.0212x; 1.0212x over previous
#include <cuda_runtime.h>
#include <cstdint>

// MeanAggregator: out[i] = sum_{j in edges[i]} nodes[edges[i][j]] / n_nodes
// Shapes: N = 40000, DEG = 16, D = 128 (fp32); edges buffer is int32.
//
// R14: every MLP/occupancy combination (R4-R13) hit the same 22.6-25us
// equilibrium -> per-SM L1tex outstanding-line capacity (~248) at loaded L2
// latency is the binding resource; per-warp knobs cannot move it. The one
// untouched cost is wave structure: grid=5000 = ~4.2 waves with ~2360-cyc
// transitions + per-wave straggler spread. This version is persistent:
// ONE wave (148 SMs x 4 blocks), each warp grid-strides over nodes, so
// there are no wave transitions and the gather stream never drains.

#define D_FEAT 128
#define D_VEC (D_FEAT / 4)   // 32 float4 per row = 1 per lane
#define DEG_FAST 16
#define SMS 148
#define BLOCKS_PER_SM 4
#define THREADS 256

__global__ __launch_bounds__(THREADS, BLOCKS_PER_SM)
void gather_mean_persist_kernel(
    const float4* __restrict__ nodes,   // [n_nodes * 32] float4
    const int* __restrict__ edges,      // [n_nodes * deg] int32
    float4* __restrict__ out,           // [n_nodes * 32] float4
    int n_nodes, int deg, float inv_n)
{
    const int lane = threadIdx.x & 31;
    const int warp_gid = (blockIdx.x * THREADS + threadIdx.x) >> 5;
    const int warp_stride = (gridDim.x * THREADS) >> 5;

    if (deg == DEG_FAST) {
        for (int node = warp_gid; node < n_nodes; node += warp_stride) {
            // Index fetch: 4 x int4 (uniform across warp -> broadcast LDG).
            const int4* e4 = (const int4*)(edges + (long long)node * DEG_FAST);
            int idx[DEG_FAST];
#pragma unroll
            for (int q = 0; q < 4; ++q) {
                int4 a = __ldg(&e4[q]);
                idx[q * 4 + 0] = a.x; idx[q * 4 + 1] = a.y;
                idx[q * 4 + 2] = a.z; idx[q * 4 + 3] = a.w;
            }

            // 16 independent float4 gathers, pairwise-tree reduce.
            float4 v[DEG_FAST];
#pragma unroll
            for (int j = 0; j < DEG_FAST; ++j) {
                v[j] = __ldg(&nodes[(size_t)(unsigned)idx[j] * D_VEC + lane]);
            }
            float4 s[8];
#pragma unroll
            for (int j = 0; j < 8; ++j) {
                s[j].x = v[2 * j].x + v[2 * j + 1].x;
                s[j].y = v[2 * j].y + v[2 * j + 1].y;
                s[j].z = v[2 * j].z + v[2 * j + 1].z;
                s[j].w = v[2 * j].w + v[2 * j + 1].w;
            }
            float4 t[4];
#pragma unroll
            for (int j = 0; j < 4; ++j) {
                t[j].x = s[2 * j].x + s[2 * j + 1].x;
                t[j].y = s[2 * j].y + s[2 * j + 1].y;
                t[j].z = s[2 * j].z + s[2 * j + 1].z;
                t[j].w = s[2 * j].w + s[2 * j + 1].w;
            }
            float4 acc;
            acc.x = (t[0].x + t[1].x) + (t[2].x + t[3].x);
            acc.y = (t[0].y + t[1].y) + (t[2].y + t[3].y);
            acc.z = (t[0].z + t[1].z) + (t[2].z + t[3].z);
            acc.w = (t[0].w + t[1].w) + (t[2].w + t[3].w);

            out[(long long)node * D_VEC + lane] =
                make_float4(acc.x * inv_n, acc.y * inv_n,
                            acc.z * inv_n, acc.w * inv_n);
        }
    } else {
        // Generic fallback.
        for (int node = warp_gid; node < n_nodes; node += warp_stride) {
            const int* e = edges + (long long)node * deg;
            float4 acc = make_float4(0.f, 0.f, 0.f, 0.f);
            int j = 0;
            for (; j + 4 <= deg; j += 4) {
                int i0 = __ldg(&e[j + 0]);
                int i1 = __ldg(&e[j + 1]);
                int i2 = __ldg(&e[j + 2]);
                int i3 = __ldg(&e[j + 3]);
                float4 v0 = __ldg(&nodes[(size_t)(unsigned)i0 * D_VEC + lane]);
                float4 v1 = __ldg(&nodes[(size_t)(unsigned)i1 * D_VEC + lane]);
                float4 v2 = __ldg(&nodes[(size_t)(unsigned)i2 * D_VEC + lane]);
                float4 v3 = __ldg(&nodes[(size_t)(unsigned)i3 * D_VEC + lane]);
                acc.x += (v0.x + v1.x) + (v2.x + v3.x);
                acc.y += (v0.y + v1.y) + (v2.y + v3.y);
                acc.z += (v0.z + v1.z) + (v2.z + v3.z);
                acc.w += (v0.w + v1.w) + (v2.w + v3.w);
            }
            for (; j < deg; ++j) {
                int i0 = __ldg(&e[j]);
                float4 v = __ldg(&nodes[(size_t)(unsigned)i0 * D_VEC + lane]);
                acc.x += v.x; acc.y += v.y; acc.z += v.z; acc.w += v.w;
            }
            out[(long long)node * D_VEC + lane] =
                make_float4(acc.x * inv_n, acc.y * inv_n,
                            acc.z * inv_n, acc.w * inv_n);
        }
    }
}

extern "C" void kernel_launch(void* const* d_in, const int* in_sizes, int n_in,
                              void* d_out, int out_size)
{
    const float4* nodes = (const float4*)d_in[0];
    const int* edges = (const int*)d_in[1];
    float4* out = (float4*)d_out;

    const int n_nodes = in_sizes[0] / D_FEAT;
    const int deg = in_sizes[1] / n_nodes;
    const float inv_n = 1.0f / (float)n_nodes;

    // Persistent single wave: 148 SMs x 4 blocks of 256 threads.
    const int blocks = SMS * BLOCKS_PER_SM;  // 592
    gather_mean_persist_kernel<<<blocks, THREADS>>>(nodes, edges, out,
                                                    n_nodes, deg, inv_n);
}